// round 13
// baseline (speedup 1.0000x reference)
#include <cuda_runtime.h>
#include <math.h>
#include <stdint.h>

#define D_IN   1024
#define D_OUT  1024
#define SEQ    2048
#define BATCH  2
#define NHEAD  16
#define HDIM   64
#define NTOK   (BATCH * SEQ)   // 4096

// Scratch (tf32 bit patterns). Q/K permuted along hd (perm8); V plain;
// ctx permuted along features (perm16); x/weights permuted along k (perm16).
__device__ uint32_t g_q[NTOK * D_OUT];
__device__ uint32_t g_k[NTOK * D_OUT];
__device__ uint32_t g_v[NTOK * D_OUT];
__device__ uint32_t g_ctx[NTOK * D_OUT];
__device__ uint32_t g_xt[NTOK * D_IN];
__device__ uint32_t g_wq[D_OUT * D_IN];
__device__ uint32_t g_wk[D_OUT * D_IN];
__device__ uint32_t g_wv[D_OUT * D_IN];
__device__ uint32_t g_wo[D_OUT * D_IN];

__device__ __forceinline__ uint32_t f2tf(float x) {
    uint32_t u;
    asm("cvt.rna.tf32.f32 %0, %1;" : "=r"(u) : "f"(x));
    return u;
}

// perm8 (attention Q/K along hd): k -> 2*(k&3) + (k>>2) within groups of 8
__device__ __forceinline__ int perm8(int e) { return ((e & 3) << 1) | ((e >> 2) & 1); }

__device__ __forceinline__ void mma8(float c[4],
                                     uint32_t a0, uint32_t a1, uint32_t a2, uint32_t a3,
                                     uint32_t b0, uint32_t b1) {
    asm volatile(
        "mma.sync.aligned.m16n8k8.row.col.f32.tf32.tf32.f32 "
        "{%0,%1,%2,%3},{%4,%5,%6,%7},{%8,%9},{%0,%1,%2,%3};"
        : "+f"(c[0]), "+f"(c[1]), "+f"(c[2]), "+f"(c[3])
        : "r"(a0), "r"(a1), "r"(a2), "r"(a3), "r"(b0), "r"(b1));
}

__device__ __forceinline__ void cp16(uint32_t dst_smem, const void* src) {
    asm volatile("cp.async.cg.shared.global [%0], [%1], 16;\n"
                 :: "r"(dst_smem), "l"(src));
}

// ---------------------------------------------------------------------------
// prep: convert x + 4 weight matrices to tf32 bits, perm16 along k.
// ---------------------------------------------------------------------------
__global__ __launch_bounds__(256) void prep_kernel(const float* __restrict__ x,
                                                   const float* __restrict__ Wq,
                                                   const float* __restrict__ Wk,
                                                   const float* __restrict__ Wv,
                                                   const float* __restrict__ Wo) {
    const size_t NX4 = (size_t)NTOK * D_IN / 4;      // 1048576
    const size_t NW4 = (size_t)D_OUT * D_IN / 4;     // 262144
    size_t i4 = (size_t)blockIdx.x * 256 + threadIdx.x;

    const float* src;
    uint32_t* dst;
    size_t rel;
    if (i4 < NX4)                { src = x;  dst = g_xt; rel = i4; }
    else if (i4 < NX4 + NW4)     { src = Wq; dst = g_wq; rel = i4 - NX4; }
    else if (i4 < NX4 + 2 * NW4) { src = Wk; dst = g_wk; rel = i4 - NX4 - NW4; }
    else if (i4 < NX4 + 3 * NW4) { src = Wv; dst = g_wv; rel = i4 - NX4 - 2 * NW4; }
    else                         { src = Wo; dst = g_wo; rel = i4 - NX4 - 3 * NW4; }

    float4 v = ((const float4*)src)[rel];
    size_t e = rel * 4;
    uint32_t* p = dst + (e & ~(size_t)15);
    int q = (int)((e >> 2) & 3);
    p[q + 0]  = f2tf(v.x);
    p[q + 4]  = f2tf(v.y);
    p[q + 8]  = f2tf(v.z);
    p[q + 12] = f2tf(v.w);
}

// ---------------------------------------------------------------------------
// GEMM mainloop: C(128x64) = A(row0..,k) * B(col0..,k)^T over K=1024.
// 256 threads, 8 warps (4m x 2n), 32x32 warp tiles (mi=2, ni=4). perm16
// operands, smem stride 16 words + row-parity XOR-8 swizzle, LDS.128 frags.
// 4-substage ring (BK=16 each), depth-3 cp.async issue, R8-proven ordering:
// wait_group -> __syncthreads -> compute(kc%4) -> issue(kc+3 -> (kc+3)%4).
// Substage: A[128][16] | B[64][16] = 12 KB; 4 substages = 48 KB.
// ---------------------------------------------------------------------------
#define GEMM_SMEM (4 * 12288)   // 48 KB

__device__ __forceinline__ void gemm_mainloop(const uint32_t* __restrict__ Ag,
                                              const uint32_t* __restrict__ Bg,
                                              int row0, int col0,
                                              uint32_t* smw, uint32_t sbase,
                                              float acc[2][4][4]) {
    const int t    = threadIdx.x;
    const int lane = t & 31;
    const int wid  = t >> 5;
    const int wm   = wid & 3;               // 0..3 -> 32-row band
    const int wn   = wid >> 2;              // 0..1 -> 32-col band
    const int g    = lane >> 2;
    const int c    = lane & 3;
    const int x8   = (g & 1) << 3;          // row-parity xor for fragments

    // A cp map: 512 cp16/substage; thread: row ra=t>>1, col half ca
    const int ra  = t >> 1;
    const int ca  = (t & 1) << 3;
    const int rax = (ra & 1) << 3;
    const uint32_t daA = sbase + 4u * (uint32_t)(ra * 16 + (ca ^ rax));
    const uint32_t daB = sbase + 4u * (uint32_t)(ra * 16 + ((ca + 4) ^ rax));
    // B cp map: 256 cp16/substage; thread: row rb=t>>2, col cb
    const int rb  = t >> 2;
    const int cb  = (t & 3) << 2;
    const int rbx = (rb & 1) << 3;
    const uint32_t dbB = sbase + 8192u + 4u * (uint32_t)(rb * 16 + (cb ^ rbx));

    const uint32_t* pa = &Ag[(size_t)(row0 + ra) * D_IN + ca];
    const uint32_t* pb = &Bg[(size_t)(col0 + rb) * D_IN + cb];

#define G_ISSUE(kc, stg)                                                   \
    {                                                                      \
        const uint32_t off = (uint32_t)(stg) * 12288u;                     \
        cp16(daA + off, pa + (kc) * 16);                                   \
        cp16(daB + off, pa + (kc) * 16 + 4);                               \
        cp16(dbB + off, pb + (kc) * 16);                                   \
        asm volatile("cp.async.commit_group;");                            \
    }

#define G_COMPUTE(stg)                                                     \
    {                                                                      \
        const uint32_t* SA = smw + (stg) * 3072;                           \
        const uint32_t* SB = SA + 2048;                                    \
        uint4 aF[2][2];                                                    \
        _Pragma("unroll")                                                  \
        for (int mi = 0; mi < 2; mi++) {                                   \
            int r = wm * 32 + mi * 16 + g;                                 \
            aF[mi][0] = *(const uint4*)&SA[r * 16 + ((4 * c) ^ x8)];       \
            aF[mi][1] = *(const uint4*)&SA[(r + 8) * 16 + ((4 * c) ^ x8)]; \
        }                                                                  \
        _Pragma("unroll")                                                  \
        for (int ni = 0; ni < 4; ni++) {                                   \
            int n = wn * 32 + ni * 8 + g;                                  \
            uint4 bF = *(const uint4*)&SB[n * 16 + ((4 * c) ^ x8)];        \
            _Pragma("unroll")                                              \
            for (int mi = 0; mi < 2; mi++) {                               \
                mma8(acc[mi][ni], aF[mi][0].x, aF[mi][1].x,                \
                     aF[mi][0].y, aF[mi][1].y, bF.x, bF.y);                \
                mma8(acc[mi][ni], aF[mi][0].z, aF[mi][1].z,                \
                     aF[mi][0].w, aF[mi][1].w, bF.z, bF.w);                \
            }                                                              \
        }                                                                  \
    }

#pragma unroll
    for (int mi = 0; mi < 2; mi++)
#pragma unroll
        for (int ni = 0; ni < 4; ni++)
#pragma unroll
            for (int j = 0; j < 4; j++) acc[mi][ni][j] = 0.f;

    G_ISSUE(0, 0); G_ISSUE(1, 1); G_ISSUE(2, 2);

    for (int kc = 0; kc < 61; kc++) {
        asm volatile("cp.async.wait_group 2;");
        __syncthreads();
        G_COMPUTE(kc & 3);
        G_ISSUE(kc + 3, (kc + 3) & 3);
    }
    asm volatile("cp.async.wait_group 2;");
    __syncthreads();
    G_COMPUTE(61 & 3);
    asm volatile("cp.async.wait_group 1;");
    __syncthreads();
    G_COMPUTE(62 & 3);
    asm volatile("cp.async.wait_group 0;");
    __syncthreads();
    G_COMPUTE(63 & 3);

#undef G_ISSUE
#undef G_COMPUTE
}

// ---------------------------------------------------------------------------
// QKV projection: out = x @ W^T. Q/K written hd-permuted (perm8), V plain,
// [B,H,S,hd]. grid: (16, 32, 3), block 256.
// ---------------------------------------------------------------------------
__global__ __launch_bounds__(256, 3) void qkv_gemm() {
    extern __shared__ uint32_t smw[];
    const uint32_t sbase = (uint32_t)__cvta_generic_to_shared(smw);

    const uint32_t* W = (blockIdx.z == 0) ? g_wq : (blockIdx.z == 1) ? g_wk : g_wv;
    uint32_t*     out = (blockIdx.z == 0) ? g_q  : (blockIdx.z == 1) ? g_k  : g_v;
    const bool permout = (blockIdx.z != 2);

    const int row0 = blockIdx.y * 128;
    const int col0 = blockIdx.x * 64;

    float acc[2][4][4];
    gemm_mainloop(g_xt, W, row0, col0, smw, sbase, acc);

    const int t    = threadIdx.x;
    const int lane = t & 31;
    const int wid  = t >> 5;
    const int wm   = wid & 3;
    const int wn   = wid >> 2;
    const int g    = lane >> 2;
    const int c    = lane & 3;
    const int b    = row0 >> 11;

#pragma unroll
    for (int mi = 0; mi < 2; mi++) {
#pragma unroll
        for (int ni = 0; ni < 4; ni++) {
            int r = row0 + wm * 32 + mi * 16 + g;
            int f = col0 + wn * 32 + ni * 8 + 2 * c;
            int h = f >> 6;
            int d = f & 63;
            uint32_t v0 = f2tf(acc[mi][ni][0]);
            uint32_t v1 = f2tf(acc[mi][ni][1]);
            uint32_t v2 = f2tf(acc[mi][ni][2]);
            uint32_t v3 = f2tf(acc[mi][ni][3]);
            int s  = r & (SEQ - 1);
            int s2 = (r + 8) & (SEQ - 1);
            size_t baseA = (((size_t)(b * NHEAD + h) * SEQ + s)  << 6);
            size_t baseB = (((size_t)(b * NHEAD + h) * SEQ + s2) << 6);
            if (permout) {
                int gb = d & ~7;
                int e0 = d & 7;
                int p0 = gb + perm8(e0), p1 = gb + perm8(e0 + 1);
                out[baseA + p0] = v0; out[baseA + p1] = v1;
                out[baseB + p0] = v2; out[baseB + p1] = v3;
            } else {
                *(uint2*)&out[baseA + d] = make_uint2(v0, v1);
                *(uint2*)&out[baseB + d] = make_uint2(v2, v3);
            }
        }
    }
}

// ---------------------------------------------------------------------------
// Output projection: d_out = ctx @ Wo^T + bo (ctx/Wo both perm16 tf32).
// grid: (16, 32), block 256.
// ---------------------------------------------------------------------------
__global__ __launch_bounds__(256, 3) void proj_gemm(const float* __restrict__ bo,
                                                    float* __restrict__ Cout) {
    extern __shared__ uint32_t smw[];
    const uint32_t sbase = (uint32_t)__cvta_generic_to_shared(smw);

    const int row0 = blockIdx.y * 128;
    const int col0 = blockIdx.x * 64;

    float acc[2][4][4];
    gemm_mainloop(g_ctx, g_wo, row0, col0, smw, sbase, acc);

    const int t    = threadIdx.x;
    const int lane = t & 31;
    const int wid  = t >> 5;
    const int wm   = wid & 3;
    const int wn   = wid >> 2;
    const int g    = lane >> 2;
    const int c    = lane & 3;

#pragma unroll
    for (int mi = 0; mi < 2; mi++) {
#pragma unroll
        for (int ni = 0; ni < 4; ni++) {
            int r = row0 + wm * 32 + mi * 16 + g;
            int f = col0 + wn * 32 + ni * 8 + 2 * c;
            float2 bb = make_float2(bo[f], bo[f + 1]);
            *(float2*)&Cout[(size_t)r * D_OUT + f] =
                make_float2(acc[mi][ni][0] + bb.x, acc[mi][ni][1] + bb.y);
            *(float2*)&Cout[(size_t)(r + 8) * D_OUT + f] =
                make_float2(acc[mi][ni][2] + bb.x, acc[mi][ni][3] + bb.y);
        }
    }
}

// ---------------------------------------------------------------------------
// Flash attention (causal), tf32 mma.sync. 128 q-rows per CTA, 4 warps of
// 32 q-rows each (mi=2), cp.async double-buffered 64-row K/V tiles.
// (unchanged — known correct)
// ---------------------------------------------------------------------------
#define AS 72
#define ATTN_SMEM ((4 * 64 + 128) * AS * 4)   // 110592 B

__global__ __launch_bounds__(128, 2) void attn_kernel() {
    extern __shared__ uint32_t smu[];
    uint32_t* Kb[2] = { smu,             smu + 2 * 64 * AS };
    uint32_t* Vb[2] = { smu + 64 * AS,   smu + 3 * 64 * AS };
    uint32_t* Ps    = smu + 4 * 64 * AS;   // 128 rows

    const int t    = threadIdx.x;
    const int lane = t & 31;
    const int w    = t >> 5;          // 0..3
    const int g    = lane >> 2;
    const int c    = lane & 3;

    const int m0 = blockIdx.x * 128;
    const int h  = blockIdx.y;
    const int b  = blockIdx.z;

    const size_t head_base = ((size_t)(b * NHEAD + h)) * SEQ * HDIM;
    const uint32_t* qb = g_q + head_base;
    const uint32_t* kb = g_k + head_base;
    const uint32_t* vb = g_v + head_base;

    // cp.async map: thread covers rows rl+8j (j=0..7), 16B column cl
    const int rl = t >> 4;            // 0..7
    const int cl = (t & 15) << 2;     // word col 0..60
    uint32_t kbase[2], vbase[2];
#pragma unroll
    for (int bf = 0; bf < 2; bf++) {
        kbase[bf] = (uint32_t)__cvta_generic_to_shared(&Kb[bf][rl * AS + cl]);
        vbase[bf] = (uint32_t)__cvta_generic_to_shared(&Vb[bf][rl * AS + cl]);
    }
    const size_t grow = (size_t)rl * HDIM + cl;

#define ISSUE_TILE(n0, bf)                                                  \
    {                                                                       \
        _Pragma("unroll")                                                   \
        for (int j = 0; j < 8; j++) {                                       \
            cp16(kbase[bf] + j * (8 * AS * 4),                              \
                 &kb[(size_t)(n0) * HDIM + grow + (size_t)j * 8 * HDIM]);   \
            cp16(vbase[bf] + j * (8 * AS * 4),                              \
                 &vb[(size_t)(n0) * HDIM + grow + (size_t)j * 8 * HDIM]);   \
        }                                                                   \
        asm volatile("cp.async.commit_group;");                             \
    }

    ISSUE_TILE(0, 0);   // overlap first K/V load with Q staging

    // Stage Q (128 rows) into Ps, lift fragments (hd permuted -> uint2)
    for (int i = t; i < 2048; i += 128) {
        int r  = i >> 4;
        int cc = (i & 15) << 2;
        *(uint4*)&Ps[r * AS + cc] = *(const uint4*)&qb[(size_t)(m0 + r) * HDIM + cc];
    }
    __syncthreads();

    uint32_t qf[8][2][4];
#pragma unroll
    for (int ks = 0; ks < 8; ks++) {
#pragma unroll
        for (int mi = 0; mi < 2; mi++) {
            int row = w * 32 + mi * 16 + g;
            uint2 qa = *(const uint2*)&Ps[row * AS + ks * 8 + 2 * c];
            uint2 qc = *(const uint2*)&Ps[(row + 8) * AS + ks * 8 + 2 * c];
            qf[ks][mi][0] = qa.x; qf[ks][mi][1] = qc.x;
            qf[ks][mi][2] = qa.y; qf[ks][mi][3] = qc.y;
        }
    }

    float o[2][8][4];
#pragma unroll
    for (int mi = 0; mi < 2; mi++)
#pragma unroll
        for (int ni = 0; ni < 8; ni++)
#pragma unroll
            for (int j = 0; j < 4; j++) o[mi][ni][j] = 0.f;
    float mr[2][2], lr[2][2];
#pragma unroll
    for (int mi = 0; mi < 2; mi++) {
        mr[mi][0] = -1e30f; mr[mi][1] = -1e30f;
        lr[mi][0] = 0.f;    lr[mi][1] = 0.f;
    }

    int rA[2], rB[2];
#pragma unroll
    for (int mi = 0; mi < 2; mi++) {
        rA[mi] = m0 + w * 32 + mi * 16 + g;
        rB[mi] = rA[mi] + 8;
    }
    const int lastrow = m0 + w * 32 + 31;
    const int NT = (m0 >> 6) + 2;

    for (int it = 0; it < NT; it++) {
        const int n0  = it << 6;
        const int cur = it & 1;
        if (it + 1 < NT) {
            ISSUE_TILE((it + 1) << 6, cur ^ 1);
            asm volatile("cp.async.wait_group 1;");
        } else {
            asm volatile("cp.async.wait_group 0;");
        }
        __syncthreads();

        if (n0 <= lastrow) {   // warp has at least one unmasked column
            const uint32_t* Ks = Kb[cur];
            const uint32_t* Vs = Vb[cur];

            // S = Q K^T  (32x64 per warp, 2 x m16)
            float s[2][8][4];
#pragma unroll
            for (int mi = 0; mi < 2; mi++)
#pragma unroll
                for (int ni = 0; ni < 8; ni++)
#pragma unroll
                    for (int j = 0; j < 4; j++) s[mi][ni][j] = 0.f;

#pragma unroll
            for (int ks = 0; ks < 8; ks++) {
#pragma unroll
                for (int ni = 0; ni < 8; ni++) {
                    uint2 bb = *(const uint2*)&Ks[(ni * 8 + g) * AS + ks * 8 + 2 * c];
#pragma unroll
                    for (int mi = 0; mi < 2; mi++)
                        mma8(s[mi][ni], qf[ks][mi][0], qf[ks][mi][1],
                             qf[ks][mi][2], qf[ks][mi][3], bb.x, bb.y);
                }
            }

#pragma unroll
            for (int mi = 0; mi < 2; mi++) {
                const bool needmask = (n0 + 63 > rA[mi]);
#pragma unroll
                for (int ni = 0; ni < 8; ni++) {
#pragma unroll
                    for (int j = 0; j < 4; j++) s[mi][ni][j] *= 0.125f;
                    if (needmask) {
                        int col = n0 + ni * 8 + 2 * c;
                        if (col     > rA[mi]) s[mi][ni][0] = -1e30f;
                        if (col + 1 > rA[mi]) s[mi][ni][1] = -1e30f;
                        if (col     > rB[mi]) s[mi][ni][2] = -1e30f;
                        if (col + 1 > rB[mi]) s[mi][ni][3] = -1e30f;
                    }
                }
            }

            // Online softmax per mi (two rows per thread, quad-reduce)
#pragma unroll
            for (int mi = 0; mi < 2; mi++) {
                float mx0 = -1e30f, mx1 = -1e30f;
#pragma unroll
                for (int ni = 0; ni < 8; ni++) {
                    mx0 = fmaxf(mx0, fmaxf(s[mi][ni][0], s[mi][ni][1]));
                    mx1 = fmaxf(mx1, fmaxf(s[mi][ni][2], s[mi][ni][3]));
                }
                mx0 = fmaxf(mx0, __shfl_xor_sync(0xffffffffu, mx0, 1));
                mx0 = fmaxf(mx0, __shfl_xor_sync(0xffffffffu, mx0, 2));
                mx1 = fmaxf(mx1, __shfl_xor_sync(0xffffffffu, mx1, 1));
                mx1 = fmaxf(mx1, __shfl_xor_sync(0xffffffffu, mx1, 2));

                float mn0 = fmaxf(mr[mi][0], mx0);
                float mn1 = fmaxf(mr[mi][1], mx1);
                float sum0 = 0.f, sum1 = 0.f;
#pragma unroll
                for (int ni = 0; ni < 8; ni++) {
                    s[mi][ni][0] = __expf(s[mi][ni][0] - mn0); sum0 += s[mi][ni][0];
                    s[mi][ni][1] = __expf(s[mi][ni][1] - mn0); sum0 += s[mi][ni][1];
                    s[mi][ni][2] = __expf(s[mi][ni][2] - mn1); sum1 += s[mi][ni][2];
                    s[mi][ni][3] = __expf(s[mi][ni][3] - mn1); sum1 += s[mi][ni][3];
                }
                sum0 += __shfl_xor_sync(0xffffffffu, sum0, 1);
                sum0 += __shfl_xor_sync(0xffffffffu, sum0, 2);
                sum1 += __shfl_xor_sync(0xffffffffu, sum1, 1);
                sum1 += __shfl_xor_sync(0xffffffffu, sum1, 2);

                float a0 = __expf(mr[mi][0] - mn0);
                float a1 = __expf(mr[mi][1] - mn1);
                lr[mi][0] = lr[mi][0] * a0 + sum0;
                lr[mi][1] = lr[mi][1] * a1 + sum1;
                mr[mi][0] = mn0; mr[mi][1] = mn1;
#pragma unroll
                for (int ni = 0; ni < 8; ni++) {
                    o[mi][ni][0] *= a0; o[mi][ni][1] *= a0;
                    o[mi][ni][2] *= a1; o[mi][ni][3] *= a1;
                }

                // P -> warp-private smem rows (tf32, plain k layout)
                int pr0 = (w * 32 + mi * 16 + g) * AS;
#pragma unroll
                for (int ni = 0; ni < 8; ni++) {
                    *(uint2*)&Ps[pr0 + ni * 8 + 2 * c] =
                        make_uint2(f2tf(s[mi][ni][0]), f2tf(s[mi][ni][1]));
                    *(uint2*)&Ps[pr0 + 8 * AS + ni * 8 + 2 * c] =
                        make_uint2(f2tf(s[mi][ni][2]), f2tf(s[mi][ni][3]));
                }
            }
            __syncwarp();

            // O += P V  (V plain; B frags shared across mi)
#pragma unroll
            for (int ks = 0; ks < 8; ks++) {
                uint32_t af[2][4];
#pragma unroll
                for (int mi = 0; mi < 2; mi++) {
                    int base = (w * 32 + mi * 16 + g) * AS + ks * 8;
                    af[mi][0] = Ps[base + c];
                    af[mi][1] = Ps[base + 8 * AS + c];
                    af[mi][2] = Ps[base + c + 4];
                    af[mi][3] = Ps[base + 8 * AS + c + 4];
                }
#pragma unroll
                for (int ni = 0; ni < 8; ni++) {
                    uint32_t b0 = Vs[(ks * 8 + c) * AS + ni * 8 + g];
                    uint32_t b1 = Vs[(ks * 8 + c + 4) * AS + ni * 8 + g];
#pragma unroll
                    for (int mi = 0; mi < 2; mi++)
                        mma8(o[mi][ni], af[mi][0], af[mi][1], af[mi][2], af[mi][3], b0, b1);
                }
            }
        }
        __syncthreads();   // buffer 'cur' free for next prefetch
    }
#undef ISSUE_TILE

    // Epilogue: normalize, write ctx feature-permuted perm16 (proj consumes it)
#pragma unroll
    for (int mi = 0; mi < 2; mi++) {
        float inv0 = 1.f / lr[mi][0];
        float inv1 = 1.f / lr[mi][1];
        const size_t pA = ((size_t)(b * SEQ + rA[mi])) * D_OUT + h * HDIM;
        const size_t pB = ((size_t)(b * SEQ + rB[mi])) * D_OUT + h * HDIM;
#pragma unroll
        for (int ni = 0; ni < 8; ni++) {
            int e0 = ni * 8 + 2 * c;
            int gb = e0 & ~15;
            int w0 = e0 & 15, w1 = w0 + 1;
            int p0 = gb + ((w0 & 3) << 2) + (w0 >> 2);
            int p1 = gb + ((w1 & 3) << 2) + (w1 >> 2);
            g_ctx[pA + p0] = f2tf(o[mi][ni][0] * inv0);
            g_ctx[pA + p1] = f2tf(o[mi][ni][1] * inv0);
            g_ctx[pB + p0] = f2tf(o[mi][ni][2] * inv1);
            g_ctx[pB + p1] = f2tf(o[mi][ni][3] * inv1);
        }
    }
}

// ---------------------------------------------------------------------------
extern "C" void kernel_launch(void* const* d_in, const int* in_sizes, int n_in,
                              void* d_out, int out_size) {
    const float* x  = (const float*)d_in[0];
    const float* Wq = (const float*)d_in[1];
    const float* Wk = (const float*)d_in[2];
    const float* Wv = (const float*)d_in[3];
    const float* Wo = (const float*)d_in[4];
    const float* bo = (const float*)d_in[5];
    float* out = (float*)d_out;

    cudaFuncSetAttribute(qkv_gemm,
                         cudaFuncAttributeMaxDynamicSharedMemorySize, GEMM_SMEM);
    cudaFuncSetAttribute(proj_gemm,
                         cudaFuncAttributeMaxDynamicSharedMemorySize, GEMM_SMEM);
    cudaFuncSetAttribute(attn_kernel,
                         cudaFuncAttributeMaxDynamicSharedMemorySize, ATTN_SMEM);

    prep_kernel<<<8192, 256>>>(x, Wq, Wk, Wv, Wo);
    qkv_gemm<<<dim3(D_OUT / 64, NTOK / 128, 3), 256, GEMM_SMEM>>>();
    attn_kernel<<<dim3(SEQ / 128, NHEAD, BATCH), 128, ATTN_SMEM>>>();
    proj_gemm<<<dim3(D_OUT / 64, NTOK / 128), 256, GEMM_SMEM>>>(bo, out);
}

// round 17
// speedup vs baseline: 1.0610x; 1.0610x over previous
#include <cuda_runtime.h>
#include <math.h>
#include <stdint.h>

#define D_IN   1024
#define D_OUT  1024
#define SEQ    2048
#define BATCH  2
#define NHEAD  16
#define HDIM   64
#define NTOK   (BATCH * SEQ)   // 4096

// Scratch (tf32 bit patterns). Q/K permuted along hd (perm8); V plain; ctx
// permuted along features (perm8); x/weights permuted along k (perm8).
__device__ uint32_t g_q[NTOK * D_OUT];
__device__ uint32_t g_k[NTOK * D_OUT];
__device__ uint32_t g_v[NTOK * D_OUT];
__device__ uint32_t g_ctx[NTOK * D_OUT];
__device__ uint32_t g_xt[NTOK * D_IN];
__device__ uint32_t g_wq[D_OUT * D_IN];
__device__ uint32_t g_wk[D_OUT * D_IN];
__device__ uint32_t g_wv[D_OUT * D_IN];
__device__ uint32_t g_wo[D_OUT * D_IN];

__device__ __forceinline__ uint32_t f2tf(float x) {
    uint32_t u;
    asm("cvt.rna.tf32.f32 %0, %1;" : "=r"(u) : "f"(x));
    return u;
}

// k-permutation within groups of 8: k -> 2*(k&3) + (k>>2)
__device__ __forceinline__ int perm8(int e) { return ((e & 3) << 1) | ((e >> 2) & 1); }

__device__ __forceinline__ void mma8(float c[4],
                                     uint32_t a0, uint32_t a1, uint32_t a2, uint32_t a3,
                                     uint32_t b0, uint32_t b1) {
    asm volatile(
        "mma.sync.aligned.m16n8k8.row.col.f32.tf32.tf32.f32 "
        "{%0,%1,%2,%3},{%4,%5,%6,%7},{%8,%9},{%0,%1,%2,%3};"
        : "+f"(c[0]), "+f"(c[1]), "+f"(c[2]), "+f"(c[3])
        : "r"(a0), "r"(a1), "r"(a2), "r"(a3), "r"(b0), "r"(b1));
}

__device__ __forceinline__ void cp16(uint32_t dst_smem, const void* src) {
    asm volatile("cp.async.cg.shared.global [%0], [%1], 16;\n"
                 :: "r"(dst_smem), "l"(src));
}

// ---------------------------------------------------------------------------
// prep: convert x + 4 weight matrices to tf32 bits with perm8 k-layout.
// ---------------------------------------------------------------------------
__global__ __launch_bounds__(256) void prep_kernel(const float* __restrict__ x,
                                                   const float* __restrict__ Wq,
                                                   const float* __restrict__ Wk,
                                                   const float* __restrict__ Wv,
                                                   const float* __restrict__ Wo) {
    const size_t NX4 = (size_t)NTOK * D_IN / 4;      // 1048576
    const size_t NW4 = (size_t)D_OUT * D_IN / 4;     // 262144
    size_t i4 = (size_t)blockIdx.x * 256 + threadIdx.x;

    const float* src;
    uint32_t* dst;
    size_t rel;
    if (i4 < NX4)                { src = x;  dst = g_xt; rel = i4; }
    else if (i4 < NX4 + NW4)     { src = Wq; dst = g_wq; rel = i4 - NX4; }
    else if (i4 < NX4 + 2 * NW4) { src = Wk; dst = g_wk; rel = i4 - NX4 - NW4; }
    else if (i4 < NX4 + 3 * NW4) { src = Wv; dst = g_wv; rel = i4 - NX4 - 2 * NW4; }
    else                         { src = Wo; dst = g_wo; rel = i4 - NX4 - 3 * NW4; }

    float4 v = ((const float4*)src)[rel];
    size_t e = rel * 4;
    uint32_t* p = dst + (e & ~(size_t)7);
    int off = (e & 4) ? 1 : 0;
    p[off + 0] = f2tf(v.x);
    p[off + 2] = f2tf(v.y);
    p[off + 4] = f2tf(v.z);
    p[off + 6] = f2tf(v.w);
}

// ---------------------------------------------------------------------------
// GEMM mainloop (R7, best measured): C(128x128) = A * B^T over K=1024.
// 256 threads, 8 warps (4m x 2n), 32x64 warp tiles. BK=16, 4-stage cp.async,
// perm8 operands, smem stride 24 words (conflict-free uint2 frags).
// smem: A stages [4][128][24] | B stages [4][128][24] = 98304 B.
// ---------------------------------------------------------------------------
#define GEMM_SMEM 98304

__device__ __forceinline__ void gemm_mainloop(const uint32_t* __restrict__ Ag,
                                              const uint32_t* __restrict__ Bg,
                                              int row0, int col0,
                                              uint32_t* smw, uint32_t sbase,
                                              float acc[2][8][4]) {
    const int t    = threadIdx.x;
    const int lane = t & 31;
    const int wid  = t >> 5;
    const int wm   = wid & 3;
    const int wn   = wid >> 2;
    const int g    = lane >> 2;
    const int c    = lane & 3;
    const int r_ld  = t >> 2;            // 0..63
    const int cc4w  = (t & 3) << 2;      // word offset 0,4,8,12

    const uint32_t thr_off = (uint32_t)(r_ld * 24 + cc4w) * 4;  // bytes
    const uint32_t* pa0 = &Ag[(size_t)(row0 + r_ld) * D_IN + cc4w];
    const uint32_t* pb0 = &Bg[(size_t)(col0 + r_ld) * D_IN + cc4w];

#define G_ISSUE(kc)                                                        \
    {                                                                      \
        uint32_t da = sbase + (((kc) & 3) * 12288) + thr_off;              \
        uint32_t db = da + 49152;                                          \
        cp16(da,        pa0 + (kc) * 16);                                  \
        cp16(da + 6144, pa0 + (kc) * 16 + (size_t)64 * D_IN);              \
        cp16(db,        pb0 + (kc) * 16);                                  \
        cp16(db + 6144, pb0 + (kc) * 16 + (size_t)64 * D_IN);              \
        asm volatile("cp.async.commit_group;");                            \
    }

#define G_COMPUTE(kc)                                                      \
    {                                                                      \
        const uint32_t* SA = smw + (((kc) & 3) * 3072);                    \
        const uint32_t* SB = SA + 12288;                                   \
        _Pragma("unroll")                                                  \
        for (int ks = 0; ks < 16; ks += 8) {                               \
            uint2 aA[2], aB[2];                                            \
            _Pragma("unroll")                                              \
            for (int mi = 0; mi < 2; mi++) {                               \
                int r = wm * 32 + mi * 16 + g;                             \
                aA[mi] = *(const uint2*)&SA[r * 24 + ks + 2 * c];          \
                aB[mi] = *(const uint2*)&SA[(r + 8) * 24 + ks + 2 * c];    \
            }                                                              \
            _Pragma("unroll")                                              \
            for (int ni = 0; ni < 8; ni++) {                               \
                int n = wn * 64 + ni * 8 + g;                              \
                uint2 bb = *(const uint2*)&SB[n * 24 + ks + 2 * c];        \
                mma8(acc[0][ni], aA[0].x, aB[0].x, aA[0].y, aB[0].y, bb.x, bb.y); \
                mma8(acc[1][ni], aA[1].x, aB[1].x, aA[1].y, aB[1].y, bb.x, bb.y); \
            }                                                              \
        }                                                                  \
    }

#pragma unroll
    for (int mi = 0; mi < 2; mi++)
#pragma unroll
        for (int ni = 0; ni < 8; ni++)
#pragma unroll
            for (int j = 0; j < 4; j++) acc[mi][ni][j] = 0.f;

    G_ISSUE(0); G_ISSUE(1); G_ISSUE(2);

    for (int kc = 0; kc < 62; kc++) {
        asm volatile("cp.async.wait_group 2;");
        __syncthreads();
        G_COMPUTE(kc);
        if (kc + 3 < 64) G_ISSUE(kc + 3);
    }
    asm volatile("cp.async.wait_group 1;");
    __syncthreads();
    G_COMPUTE(62);
    asm volatile("cp.async.wait_group 0;");
    __syncthreads();
    G_COMPUTE(63);

#undef G_ISSUE
#undef G_COMPUTE
}

// ---------------------------------------------------------------------------
// QKV projection: out = x @ W^T. Q/K written hd-permuted (perm8), V plain,
// [B,H,S,hd]. grid: (8, 32, 3), block 256.
// ---------------------------------------------------------------------------
__global__ __launch_bounds__(256, 2) void qkv_gemm() {
    extern __shared__ uint32_t smw[];
    const uint32_t sbase = (uint32_t)__cvta_generic_to_shared(smw);

    const uint32_t* W = (blockIdx.z == 0) ? g_wq : (blockIdx.z == 1) ? g_wk : g_wv;
    uint32_t*     out = (blockIdx.z == 0) ? g_q  : (blockIdx.z == 1) ? g_k  : g_v;
    const bool permout = (blockIdx.z != 2);

    const int row0 = blockIdx.y * 128;
    const int col0 = blockIdx.x * 128;

    float acc[2][8][4];
    gemm_mainloop(g_xt, W, row0, col0, smw, sbase, acc);

    const int t    = threadIdx.x;
    const int lane = t & 31;
    const int wid  = t >> 5;
    const int wm   = wid & 3;
    const int wn   = wid >> 2;
    const int g    = lane >> 2;
    const int c    = lane & 3;
    const int b    = row0 >> 11;

#pragma unroll
    for (int mi = 0; mi < 2; mi++) {
#pragma unroll
        for (int ni = 0; ni < 8; ni++) {
            int r = row0 + wm * 32 + mi * 16 + g;
            int f = col0 + wn * 64 + ni * 8 + 2 * c;
            int h = f >> 6;
            int d = f & 63;
            uint32_t v0 = f2tf(acc[mi][ni][0]);
            uint32_t v1 = f2tf(acc[mi][ni][1]);
            uint32_t v2 = f2tf(acc[mi][ni][2]);
            uint32_t v3 = f2tf(acc[mi][ni][3]);
            int s  = r & (SEQ - 1);
            int s2 = (r + 8) & (SEQ - 1);
            size_t baseA = (((size_t)(b * NHEAD + h) * SEQ + s)  << 6);
            size_t baseB = (((size_t)(b * NHEAD + h) * SEQ + s2) << 6);
            if (permout) {
                int gb = d & ~7;
                int e0 = d & 7;
                int p0 = gb + perm8(e0), p1 = gb + perm8(e0 + 1);
                out[baseA + p0] = v0; out[baseA + p1] = v1;
                out[baseB + p0] = v2; out[baseB + p1] = v3;
            } else {
                *(uint2*)&out[baseA + d] = make_uint2(v0, v1);
                *(uint2*)&out[baseB + d] = make_uint2(v2, v3);
            }
        }
    }
}

// ---------------------------------------------------------------------------
// Output projection: d_out = ctx @ Wo^T + bo (ctx/Wo both perm8 tf32).
// grid: (8, 32), block 256.
// ---------------------------------------------------------------------------
__global__ __launch_bounds__(256, 2) void proj_gemm(const float* __restrict__ bo,
                                                    float* __restrict__ Cout) {
    extern __shared__ uint32_t smw[];
    const uint32_t sbase = (uint32_t)__cvta_generic_to_shared(smw);

    const int row0 = blockIdx.y * 128;
    const int col0 = blockIdx.x * 128;

    float acc[2][8][4];
    gemm_mainloop(g_ctx, g_wo, row0, col0, smw, sbase, acc);

    const int t    = threadIdx.x;
    const int lane = t & 31;
    const int wid  = t >> 5;
    const int wm   = wid & 3;
    const int wn   = wid >> 2;
    const int g    = lane >> 2;
    const int c    = lane & 3;

#pragma unroll
    for (int mi = 0; mi < 2; mi++) {
#pragma unroll
        for (int ni = 0; ni < 8; ni++) {
            int r = row0 + wm * 32 + mi * 16 + g;
            int f = col0 + wn * 64 + ni * 8 + 2 * c;
            float2 bb = make_float2(bo[f], bo[f + 1]);
            *(float2*)&Cout[(size_t)r * D_OUT + f] =
                make_float2(acc[mi][ni][0] + bb.x, acc[mi][ni][1] + bb.y);
            *(float2*)&Cout[(size_t)(r + 8) * D_OUT + f] =
                make_float2(acc[mi][ni][2] + bb.x, acc[mi][ni][3] + bb.y);
        }
    }
}

// ---------------------------------------------------------------------------
// Flash attention (R8, best measured): causal, tf32 mma.sync. 128 q-rows per
// CTA, 4 warps of 32 q-rows each (mi=2), cp.async double-buffered 64-row K/V.
// Smem (words): K0|V0|K1|V1 (64x72 each) | Ps (128x72).
// grid: (SEQ/128, NHEAD, BATCH), block 128.
// ---------------------------------------------------------------------------
#define AS 72
#define ATTN_SMEM ((4 * 64 + 128) * AS * 4)   // 110592 B

__global__ __launch_bounds__(128, 2) void attn_kernel() {
    extern __shared__ uint32_t smu[];
    uint32_t* Kb[2] = { smu,             smu + 2 * 64 * AS };
    uint32_t* Vb[2] = { smu + 64 * AS,   smu + 3 * 64 * AS };
    uint32_t* Ps    = smu + 4 * 64 * AS;   // 128 rows

    const int t    = threadIdx.x;
    const int lane = t & 31;
    const int w    = t >> 5;          // 0..3
    const int g    = lane >> 2;
    const int c    = lane & 3;

    const int m0 = blockIdx.x * 128;
    const int h  = blockIdx.y;
    const int b  = blockIdx.z;

    const size_t head_base = ((size_t)(b * NHEAD + h)) * SEQ * HDIM;
    const uint32_t* qb = g_q + head_base;
    const uint32_t* kb = g_k + head_base;
    const uint32_t* vb = g_v + head_base;

    // cp.async map: thread covers rows rl+8j (j=0..7), 16B column cl
    const int rl = t >> 4;            // 0..7
    const int cl = (t & 15) << 2;     // word col 0..60
    uint32_t kbase[2], vbase[2];
#pragma unroll
    for (int bf = 0; bf < 2; bf++) {
        kbase[bf] = (uint32_t)__cvta_generic_to_shared(&Kb[bf][rl * AS + cl]);
        vbase[bf] = (uint32_t)__cvta_generic_to_shared(&Vb[bf][rl * AS + cl]);
    }
    const size_t grow = (size_t)rl * HDIM + cl;

#define ISSUE_TILE(n0, bf)                                                  \
    {                                                                       \
        _Pragma("unroll")                                                   \
        for (int j = 0; j < 8; j++) {                                       \
            cp16(kbase[bf] + j * (8 * AS * 4),                              \
                 &kb[(size_t)(n0) * HDIM + grow + (size_t)j * 8 * HDIM]);   \
            cp16(vbase[bf] + j * (8 * AS * 4),                              \
                 &vb[(size_t)(n0) * HDIM + grow + (size_t)j * 8 * HDIM]);   \
        }                                                                   \
        asm volatile("cp.async.commit_group;");                             \
    }

    ISSUE_TILE(0, 0);   // overlap first K/V load with Q staging

    // Stage Q (128 rows) into Ps, lift fragments (hd permuted -> uint2)
    for (int i = t; i < 2048; i += 128) {
        int r  = i >> 4;
        int cc = (i & 15) << 2;
        *(uint4*)&Ps[r * AS + cc] = *(const uint4*)&qb[(size_t)(m0 + r) * HDIM + cc];
    }
    __syncthreads();

    uint32_t qf[8][2][4];
#pragma unroll
    for (int ks = 0; ks < 8; ks++) {
#pragma unroll
        for (int mi = 0; mi < 2; mi++) {
            int row = w * 32 + mi * 16 + g;
            uint2 qa = *(const uint2*)&Ps[row * AS + ks * 8 + 2 * c];
            uint2 qc = *(const uint2*)&Ps[(row + 8) * AS + ks * 8 + 2 * c];
            qf[ks][mi][0] = qa.x; qf[ks][mi][1] = qc.x;
            qf[ks][mi][2] = qa.y; qf[ks][mi][3] = qc.y;
        }
    }

    float o[2][8][4];
#pragma unroll
    for (int mi = 0; mi < 2; mi++)
#pragma unroll
        for (int ni = 0; ni < 8; ni++)
#pragma unroll
            for (int j = 0; j < 4; j++) o[mi][ni][j] = 0.f;
    float mr[2][2], lr[2][2];
#pragma unroll
    for (int mi = 0; mi < 2; mi++) {
        mr[mi][0] = -1e30f; mr[mi][1] = -1e30f;
        lr[mi][0] = 0.f;    lr[mi][1] = 0.f;
    }

    int rA[2], rB[2];
#pragma unroll
    for (int mi = 0; mi < 2; mi++) {
        rA[mi] = m0 + w * 32 + mi * 16 + g;
        rB[mi] = rA[mi] + 8;
    }
    const int lastrow = m0 + w * 32 + 31;
    const int NT = (m0 >> 6) + 2;

    for (int it = 0; it < NT; it++) {
        const int n0  = it << 6;
        const int cur = it & 1;
        if (it + 1 < NT) {
            ISSUE_TILE((it + 1) << 6, cur ^ 1);
            asm volatile("cp.async.wait_group 1;");
        } else {
            asm volatile("cp.async.wait_group 0;");
        }
        __syncthreads();

        if (n0 <= lastrow) {   // warp has at least one unmasked column
            const uint32_t* Ks = Kb[cur];
            const uint32_t* Vs = Vb[cur];

            // S = Q K^T  (32x64 per warp, 2 x m16)
            float s[2][8][4];
#pragma unroll
            for (int mi = 0; mi < 2; mi++)
#pragma unroll
                for (int ni = 0; ni < 8; ni++)
#pragma unroll
                    for (int j = 0; j < 4; j++) s[mi][ni][j] = 0.f;

#pragma unroll
            for (int ks = 0; ks < 8; ks++) {
#pragma unroll
                for (int ni = 0; ni < 8; ni++) {
                    uint2 bb = *(const uint2*)&Ks[(ni * 8 + g) * AS + ks * 8 + 2 * c];
#pragma unroll
                    for (int mi = 0; mi < 2; mi++)
                        mma8(s[mi][ni], qf[ks][mi][0], qf[ks][mi][1],
                             qf[ks][mi][2], qf[ks][mi][3], bb.x, bb.y);
                }
            }

#pragma unroll
            for (int mi = 0; mi < 2; mi++) {
                const bool needmask = (n0 + 63 > rA[mi]);
#pragma unroll
                for (int ni = 0; ni < 8; ni++) {
#pragma unroll
                    for (int j = 0; j < 4; j++) s[mi][ni][j] *= 0.125f;
                    if (needmask) {
                        int col = n0 + ni * 8 + 2 * c;
                        if (col     > rA[mi]) s[mi][ni][0] = -1e30f;
                        if (col + 1 > rA[mi]) s[mi][ni][1] = -1e30f;
                        if (col     > rB[mi]) s[mi][ni][2] = -1e30f;
                        if (col + 1 > rB[mi]) s[mi][ni][3] = -1e30f;
                    }
                }
            }

            // Online softmax per mi (two rows per thread, quad-reduce)
#pragma unroll
            for (int mi = 0; mi < 2; mi++) {
                float mx0 = -1e30f, mx1 = -1e30f;
#pragma unroll
                for (int ni = 0; ni < 8; ni++) {
                    mx0 = fmaxf(mx0, fmaxf(s[mi][ni][0], s[mi][ni][1]));
                    mx1 = fmaxf(mx1, fmaxf(s[mi][ni][2], s[mi][ni][3]));
                }
                mx0 = fmaxf(mx0, __shfl_xor_sync(0xffffffffu, mx0, 1));
                mx0 = fmaxf(mx0, __shfl_xor_sync(0xffffffffu, mx0, 2));
                mx1 = fmaxf(mx1, __shfl_xor_sync(0xffffffffu, mx1, 1));
                mx1 = fmaxf(mx1, __shfl_xor_sync(0xffffffffu, mx1, 2));

                float mn0 = fmaxf(mr[mi][0], mx0);
                float mn1 = fmaxf(mr[mi][1], mx1);
                float sum0 = 0.f, sum1 = 0.f;
#pragma unroll
                for (int ni = 0; ni < 8; ni++) {
                    s[mi][ni][0] = __expf(s[mi][ni][0] - mn0); sum0 += s[mi][ni][0];
                    s[mi][ni][1] = __expf(s[mi][ni][1] - mn0); sum0 += s[mi][ni][1];
                    s[mi][ni][2] = __expf(s[mi][ni][2] - mn1); sum1 += s[mi][ni][2];
                    s[mi][ni][3] = __expf(s[mi][ni][3] - mn1); sum1 += s[mi][ni][3];
                }
                sum0 += __shfl_xor_sync(0xffffffffu, sum0, 1);
                sum0 += __shfl_xor_sync(0xffffffffu, sum0, 2);
                sum1 += __shfl_xor_sync(0xffffffffu, sum1, 1);
                sum1 += __shfl_xor_sync(0xffffffffu, sum1, 2);

                float a0 = __expf(mr[mi][0] - mn0);
                float a1 = __expf(mr[mi][1] - mn1);
                lr[mi][0] = lr[mi][0] * a0 + sum0;
                lr[mi][1] = lr[mi][1] * a1 + sum1;
                mr[mi][0] = mn0; mr[mi][1] = mn1;
#pragma unroll
                for (int ni = 0; ni < 8; ni++) {
                    o[mi][ni][0] *= a0; o[mi][ni][1] *= a0;
                    o[mi][ni][2] *= a1; o[mi][ni][3] *= a1;
                }

                // P -> warp-private smem rows (tf32, plain k layout)
                int pr0 = (w * 32 + mi * 16 + g) * AS;
#pragma unroll
                for (int ni = 0; ni < 8; ni++) {
                    *(uint2*)&Ps[pr0 + ni * 8 + 2 * c] =
                        make_uint2(f2tf(s[mi][ni][0]), f2tf(s[mi][ni][1]));
                    *(uint2*)&Ps[pr0 + 8 * AS + ni * 8 + 2 * c] =
                        make_uint2(f2tf(s[mi][ni][2]), f2tf(s[mi][ni][3]));
                }
            }
            __syncwarp();

            // O += P V  (V plain; B frags shared across mi)
#pragma unroll
            for (int ks = 0; ks < 8; ks++) {
                uint32_t af[2][4];
#pragma unroll
                for (int mi = 0; mi < 2; mi++) {
                    int base = (w * 32 + mi * 16 + g) * AS + ks * 8;
                    af[mi][0] = Ps[base + c];
                    af[mi][1] = Ps[base + 8 * AS + c];
                    af[mi][2] = Ps[base + c + 4];
                    af[mi][3] = Ps[base + 8 * AS + c + 4];
                }
#pragma unroll
                for (int ni = 0; ni < 8; ni++) {
                    uint32_t b0 = Vs[(ks * 8 + c) * AS + ni * 8 + g];
                    uint32_t b1 = Vs[(ks * 8 + c + 4) * AS + ni * 8 + g];
#pragma unroll
                    for (int mi = 0; mi < 2; mi++)
                        mma8(o[mi][ni], af[mi][0], af[mi][1], af[mi][2], af[mi][3], b0, b1);
                }
            }
        }
        __syncthreads();   // buffer 'cur' free for next prefetch
    }
#undef ISSUE_TILE

    // Epilogue: normalize, write ctx feature-permuted (perm8; proj consumes it)
#pragma unroll
    for (int mi = 0; mi < 2; mi++) {
        float inv0 = 1.f / lr[mi][0];
        float inv1 = 1.f / lr[mi][1];
        const size_t pA = ((size_t)(b * SEQ + rA[mi])) * D_OUT + h * HDIM;
        const size_t pB = ((size_t)(b * SEQ + rB[mi])) * D_OUT + h * HDIM;
#pragma unroll
        for (int ni = 0; ni < 8; ni++) {
            int e0 = ni * 8 + 2 * c;
            int gb = e0 & ~7;
            int p0 = gb + perm8(e0 & 7);
            int p1 = gb + perm8((e0 & 7) + 1);
            g_ctx[pA + p0] = f2tf(o[mi][ni][0] * inv0);
            g_ctx[pA + p1] = f2tf(o[mi][ni][1] * inv0);
            g_ctx[pB + p0] = f2tf(o[mi][ni][2] * inv1);
            g_ctx[pB + p1] = f2tf(o[mi][ni][3] * inv1);
        }
    }
}

// ---------------------------------------------------------------------------
extern "C" void kernel_launch(void* const* d_in, const int* in_sizes, int n_in,
                              void* d_out, int out_size) {
    const float* x  = (const float*)d_in[0];
    const float* Wq = (const float*)d_in[1];
    const float* Wk = (const float*)d_in[2];
    const float* Wv = (const float*)d_in[3];
    const float* Wo = (const float*)d_in[4];
    const float* bo = (const float*)d_in[5];
    float* out = (float*)d_out;

    cudaFuncSetAttribute(qkv_gemm,
                         cudaFuncAttributeMaxDynamicSharedMemorySize, GEMM_SMEM);
    cudaFuncSetAttribute(proj_gemm,
                         cudaFuncAttributeMaxDynamicSharedMemorySize, GEMM_SMEM);
    cudaFuncSetAttribute(attn_kernel,
                         cudaFuncAttributeMaxDynamicSharedMemorySize, ATTN_SMEM);

    prep_kernel<<<8192, 256>>>(x, Wq, Wk, Wv, Wo);
    qkv_gemm<<<dim3(D_OUT / 128, NTOK / 128, 3), 256, GEMM_SMEM>>>();
    attn_kernel<<<dim3(SEQ / 128, NHEAD, BATCH), 128, ATTN_SMEM>>>();
    proj_gemm<<<dim3(D_OUT / 128, NTOK / 128), 256, GEMM_SMEM>>>(bo, out);
}